// round 1
// baseline (speedup 1.0000x reference)
#include <cuda_runtime.h>

#define DIM 256
#define BATCH 2
#define M_ROWS (BATCH * DIM * DIM)   // 131072
#define HID (4 * DIM)                // 1024
#define EPS_LN 1e-5f

// Scratch (no cudaMalloc allowed): conv+LN output, MLP hidden.
__device__ float g_Y[(size_t)M_ROWS * DIM];        // 33.5M floats (134 MB)
__device__ float g_H[(size_t)M_ROWS * HID];        // 134M floats (537 MB)

// ---------------------------------------------------------------------------
// Kernel 1: depthwise 7x7 conv + bias + LayerNorm over W.
// One block = one output row (b, c, h, :). 256 threads = 256 w positions.
// ---------------------------------------------------------------------------
__global__ __launch_bounds__(256) void conv_ln_kernel(
    const float* __restrict__ x, const float* __restrict__ cw,
    const float* __restrict__ cb, const float* __restrict__ g,
    const float* __restrict__ bta, float* __restrict__ Y)
{
    __shared__ float s[7 * 262];
    __shared__ float wts[49];
    __shared__ float red[16];

    const int h = blockIdx.x, c = blockIdx.y, b = blockIdx.z;
    const int tid = threadIdx.x;

    if (tid < 49) wts[tid] = cw[c * 49 + tid];

    const float* xp = x + ((size_t)(b * DIM + c)) * DIM * DIM;
    for (int i = tid; i < 7 * 262; i += 256) {
        int r = i / 262, col = i - r * 262;
        int hh = h - 3 + r, ww = col - 3;
        float v = 0.f;
        if (hh >= 0 && hh < DIM && ww >= 0 && ww < DIM)
            v = xp[hh * DIM + ww];
        s[i] = v;
    }
    __syncthreads();

    float acc = cb[c];
#pragma unroll
    for (int kh = 0; kh < 7; kh++)
#pragma unroll
        for (int kw = 0; kw < 7; kw++)
            acc += s[kh * 262 + tid + kw] * wts[kh * 7 + kw];

    // LayerNorm over the 256 threads (= W axis)
    float sv = acc, sq = acc * acc;
#pragma unroll
    for (int o = 16; o; o >>= 1) {
        sv += __shfl_xor_sync(0xffffffffu, sv, o);
        sq += __shfl_xor_sync(0xffffffffu, sq, o);
    }
    int warp = tid >> 5, lane = tid & 31;
    if (lane == 0) { red[warp] = sv; red[8 + warp] = sq; }
    __syncthreads();
    float S = 0.f, S2 = 0.f;
#pragma unroll
    for (int i = 0; i < 8; i++) { S += red[i]; S2 += red[8 + i]; }
    float mu  = S * (1.f / 256.f);
    float var = S2 * (1.f / 256.f) - mu * mu;
    float inv = rsqrtf(var + EPS_LN);
    float out = (acc - mu) * inv * g[tid] + bta[tid];

    Y[(((size_t)(b * DIM + c)) * DIM + h) * DIM + tid] = out;
}

// ---------------------------------------------------------------------------
// Kernel 2/3: fp32 SIMT GEMM, C[M,N] = A[M,K] @ Bm[N,K]^T (+ epilogue).
// 128x128 block tile, BK=16, 8x8 per thread, 256 threads.
// EPI==0: v = gelu(v + bias[n]) -> C row-major [M,N]
// EPI==1: v = v + bias[n] + x[b,n,c,h]; C[b,n,c,h] = v (transposed residual)
// ---------------------------------------------------------------------------
__device__ __forceinline__ float gelu_exact(float v) {
    return 0.5f * v * (1.f + erff(v * 0.70710678118654752f));
}

template<int K, int EPI>
__global__ __launch_bounds__(256) void gemm_kernel(
    const float* __restrict__ A, const float* __restrict__ Bm,
    const float* __restrict__ bias, const float* __restrict__ xres,
    float* __restrict__ C, int N)
{
    constexpr int BM = 128, BN = 128, BK = 16;
    __shared__ float As[BK * BM];
    __shared__ float Bs[BK * BN];

    const int tid = threadIdx.x;
    const int m0 = blockIdx.y * BM;
    const int n0 = blockIdx.x * BN;
    const int tr = (tid / 16) * 8;      // row offset in tile
    const int tc = (tid % 16) * 8;      // col offset in tile
    const int lr = tid >> 2;            // loader row 0..63
    const int lc = (tid & 3) * 4;       // loader k offset {0,4,8,12}

    const float* Ag = A  + (size_t)(m0 + lr) * K + lc;
    const float* Bg = Bm + (size_t)(n0 + lr) * K + lc;

    float acc[8][8] = {};

    for (int kt = 0; kt < K; kt += BK) {
        float4 a0 = *(const float4*)(Ag + kt);
        float4 a1 = *(const float4*)(Ag + kt + (size_t)64 * K);
        float4 b0 = *(const float4*)(Bg + kt);
        float4 b1 = *(const float4*)(Bg + kt + (size_t)64 * K);
        __syncthreads();
        As[(lc + 0) * BM + lr] = a0.x; As[(lc + 1) * BM + lr] = a0.y;
        As[(lc + 2) * BM + lr] = a0.z; As[(lc + 3) * BM + lr] = a0.w;
        As[(lc + 0) * BM + lr + 64] = a1.x; As[(lc + 1) * BM + lr + 64] = a1.y;
        As[(lc + 2) * BM + lr + 64] = a1.z; As[(lc + 3) * BM + lr + 64] = a1.w;
        Bs[(lc + 0) * BN + lr] = b0.x; Bs[(lc + 1) * BN + lr] = b0.y;
        Bs[(lc + 2) * BN + lr] = b0.z; Bs[(lc + 3) * BN + lr] = b0.w;
        Bs[(lc + 0) * BN + lr + 64] = b1.x; Bs[(lc + 1) * BN + lr + 64] = b1.y;
        Bs[(lc + 2) * BN + lr + 64] = b1.z; Bs[(lc + 3) * BN + lr + 64] = b1.w;
        __syncthreads();

#pragma unroll
        for (int k = 0; k < BK; k++) {
            float4 av0 = *(const float4*)&As[k * BM + tr];
            float4 av1 = *(const float4*)&As[k * BM + tr + 4];
            float4 bv0 = *(const float4*)&Bs[k * BN + tc];
            float4 bv1 = *(const float4*)&Bs[k * BN + tc + 4];
            float a[8] = {av0.x, av0.y, av0.z, av0.w, av1.x, av1.y, av1.z, av1.w};
            float bb[8] = {bv0.x, bv0.y, bv0.z, bv0.w, bv1.x, bv1.y, bv1.z, bv1.w};
#pragma unroll
            for (int i = 0; i < 8; i++)
#pragma unroll
                for (int j = 0; j < 8; j++)
                    acc[i][j] += a[i] * bb[j];
        }
    }

    if (EPI == 0) {
        // + bias, exact GELU, store row-major
#pragma unroll
        for (int i = 0; i < 8; i++) {
            size_t row = (size_t)(m0 + tr + i) * N + n0 + tc;
            float o[8];
#pragma unroll
            for (int j = 0; j < 8; j++) {
                float v = acc[i][j] + bias[n0 + tc + j];
                o[j] = gelu_exact(v);
            }
            *(float4*)&C[row]     = make_float4(o[0], o[1], o[2], o[3]);
            *(float4*)&C[row + 4] = make_float4(o[4], o[5], o[6], o[7]);
        }
    } else {
        // + bias, transposed residual: out[b, n, c, h] = x[b,n,c,h] + v
        // m = b*65536 + c*256 + h; tile rows share (b, c).
        const int bb_ = m0 >> 16;
        const int cc  = (m0 >> 8) & 255;
        const int h0  = (m0 & 255) + tr;
#pragma unroll
        for (int j = 0; j < 8; j++) {
            int n = n0 + tc + j;
            float bj = bias[n];
            size_t base = ((size_t)bb_ << 24) + ((size_t)n << 16)
                        + ((size_t)cc << 8) + (size_t)h0;
            float4 x0 = *(const float4*)&xres[base];
            float4 x1 = *(const float4*)&xres[base + 4];
            float4 o0 = make_float4(acc[0][j] + bj + x0.x, acc[1][j] + bj + x0.y,
                                    acc[2][j] + bj + x0.z, acc[3][j] + bj + x0.w);
            float4 o1 = make_float4(acc[4][j] + bj + x1.x, acc[5][j] + bj + x1.y,
                                    acc[6][j] + bj + x1.z, acc[7][j] + bj + x1.w);
            *(float4*)&C[base]     = o0;
            *(float4*)&C[base + 4] = o1;
        }
    }
}

// ---------------------------------------------------------------------------
extern "C" void kernel_launch(void* const* d_in, const int* in_sizes, int n_in,
                              void* d_out, int out_size)
{
    (void)in_sizes; (void)n_in; (void)out_size;
    const float* x   = (const float*)d_in[0];
    const float* cw  = (const float*)d_in[1];
    const float* cb  = (const float*)d_in[2];
    const float* g   = (const float*)d_in[3];
    const float* bta = (const float*)d_in[4];
    const float* w1  = (const float*)d_in[5];
    const float* b1  = (const float*)d_in[6];
    const float* w2  = (const float*)d_in[7];
    const float* b2  = (const float*)d_in[8];
    float* out = (float*)d_out;

    float *Y = nullptr, *H = nullptr;
    cudaGetSymbolAddress((void**)&Y, g_Y);
    cudaGetSymbolAddress((void**)&H, g_H);

    // 1) depthwise conv + bias + LayerNorm(W)
    conv_ln_kernel<<<dim3(DIM, DIM, BATCH), 256>>>(x, cw, cb, g, bta, Y);

    // 2) GEMM1 (K=256 -> N=1024) + bias + exact GELU
    gemm_kernel<DIM, 0><<<dim3(HID / 128, M_ROWS / 128), 256>>>(
        Y, w1, b1, nullptr, H, HID);

    // 3) GEMM2 (K=1024 -> N=256) + bias + transposed residual into out
    gemm_kernel<HID, 1><<<dim3(DIM / 128, M_ROWS / 128), 256>>>(
        H, w2, b2, x, out, DIM);
}

// round 3
// speedup vs baseline: 1.6933x; 1.6933x over previous
#include <cuda_runtime.h>
#include <cstdint>

#define DIM 256
#define BATCH 2
#define M_ROWS (BATCH * DIM * DIM)   // 131072
#define HID (4 * DIM)                // 1024
#define EPS_LN 1e-5f

// Scratch (no cudaMalloc allowed)
__device__ __align__(256) float g_Y[(size_t)M_ROWS * DIM];   // conv+LN out (134 MB)
__device__ __align__(256) float g_H[(size_t)M_ROWS * HID];   // MLP hidden (537 MB)
__device__ __align__(256) float g_W1[(size_t)HID * DIM];     // tf32-rounded w1
__device__ __align__(256) float g_W2[(size_t)DIM * HID];     // tf32-rounded w2

// ---------------------------------------------------------------------------
// helpers
// ---------------------------------------------------------------------------
__device__ __forceinline__ uint32_t smem_u32(const void* p) {
    uint32_t a;
    asm("{ .reg .u64 t; cvta.to.shared.u64 t, %1; cvt.u32.u64 %0, t; }"
        : "=r"(a) : "l"(p));
    return a;
}
__device__ __forceinline__ void cp16(uint32_t dst, const void* src) {
    asm volatile("cp.async.cg.shared.global [%0], [%1], 16;"
                 :: "r"(dst), "l"(src) : "memory");
}
__device__ __forceinline__ void cp_commit() {
    asm volatile("cp.async.commit_group;" ::: "memory");
}
template<int N> __device__ __forceinline__ void cp_wait() {
    asm volatile("cp.async.wait_group %0;" :: "n"(N) : "memory");
}
__device__ __forceinline__ float tf32_rna(float v) {
    uint32_t u;
    asm("cvt.rna.tf32.f32 %0, %1;" : "=r"(u) : "f"(v));
    return __uint_as_float(u);
}
__device__ __forceinline__ void mma_tf32(float* c, uint32_t a0, uint32_t a1,
                                         uint32_t a2, uint32_t a3,
                                         uint32_t b0, uint32_t b1) {
    asm volatile(
        "mma.sync.aligned.m16n8k8.row.col.f32.tf32.tf32.f32 "
        "{%0,%1,%2,%3}, {%4,%5,%6,%7}, {%8,%9}, {%0,%1,%2,%3};"
        : "+f"(c[0]), "+f"(c[1]), "+f"(c[2]), "+f"(c[3])
        : "r"(a0), "r"(a1), "r"(a2), "r"(a3), "r"(b0), "r"(b1));
}
__device__ __forceinline__ float gelu_exact(float v) {
    return 0.5f * v * (1.f + erff(v * 0.70710678118654752f));
}

// ---------------------------------------------------------------------------
// tf32 rounding prep for weights
// ---------------------------------------------------------------------------
__global__ void round_tf32_kernel(const float* __restrict__ src,
                                  float* __restrict__ dst, int n) {
    int i = blockIdx.x * blockDim.x + threadIdx.x;
    if (i < n) dst[i] = tf32_rna(src[i]);
}

// ---------------------------------------------------------------------------
// Kernel 1: depthwise 7x7 conv + bias + LayerNorm over W.
// Output rounded to tf32 (it only feeds GEMM1's A operand).
// ---------------------------------------------------------------------------
__global__ __launch_bounds__(256) void conv_ln_kernel(
    const float* __restrict__ x, const float* __restrict__ cw,
    const float* __restrict__ cb, const float* __restrict__ g,
    const float* __restrict__ bta, float* __restrict__ Y)
{
    __shared__ float s[7 * 262];
    __shared__ float wts[49];
    __shared__ float red[16];

    const int h = blockIdx.x, c = blockIdx.y, b = blockIdx.z;
    const int tid = threadIdx.x;

    if (tid < 49) wts[tid] = cw[c * 49 + tid];

    const float* xp = x + ((size_t)(b * DIM + c)) * DIM * DIM;
    for (int i = tid; i < 7 * 262; i += 256) {
        int r = i / 262, col = i - r * 262;
        int hh = h - 3 + r, ww = col - 3;
        float v = 0.f;
        if (hh >= 0 && hh < DIM && ww >= 0 && ww < DIM)
            v = xp[hh * DIM + ww];
        s[i] = v;
    }
    __syncthreads();

    float acc = cb[c];
#pragma unroll
    for (int kh = 0; kh < 7; kh++)
#pragma unroll
        for (int kw = 0; kw < 7; kw++)
            acc += s[kh * 262 + tid + kw] * wts[kh * 7 + kw];

    float sv = acc, sq = acc * acc;
#pragma unroll
    for (int o = 16; o; o >>= 1) {
        sv += __shfl_xor_sync(0xffffffffu, sv, o);
        sq += __shfl_xor_sync(0xffffffffu, sq, o);
    }
    int warp = tid >> 5, lane = tid & 31;
    if (lane == 0) { red[warp] = sv; red[8 + warp] = sq; }
    __syncthreads();
    float S = 0.f, S2 = 0.f;
#pragma unroll
    for (int i = 0; i < 8; i++) { S += red[i]; S2 += red[8 + i]; }
    float mu  = S * (1.f / 256.f);
    float var = S2 * (1.f / 256.f) - mu * mu;
    float inv = rsqrtf(var + EPS_LN);
    float out = (acc - mu) * inv * g[tid] + bta[tid];

    Y[(((size_t)(b * DIM + c)) * DIM + h) * DIM + tid] = tf32_rna(out);
}

// ---------------------------------------------------------------------------
// mma.sync tf32 GEMM: C[M,N] = A[M,K] @ Bm[N,K]^T with fused epilogue.
// 128x128 CTA tile, BK=32, 2-stage cp.async pipeline, 8 warps (2m x 4n),
// warp tile 64x32 built from m16n8k8 MMAs.
// SMEM layout per operand: [kg][row][4] floats (kg = k/4) -> conflict-free
// scalar LDS for all fragments.
// EPI==0: gelu(acc + bias[n]) rounded to tf32 -> C row-major [M, NOUT]
// EPI==1: acc + bias[n] + x -> transposed residual store out[b,n,c,h]
// ---------------------------------------------------------------------------
template<int K, int NOUT, int EPI>
__global__ void __launch_bounds__(256, 2) gemm_mma(
    const float* __restrict__ A, const float* __restrict__ Bm,
    const float* __restrict__ bias, const float* __restrict__ xres,
    float* __restrict__ C)
{
    constexpr int KC = 32, NCH = K / KC;
    extern __shared__ float sm[];   // stage s: A at s*8192, B at s*8192+4096

    const int tid = threadIdx.x;
    const int m0 = blockIdx.y * 128, n0 = blockIdx.x * 128;

    // ---- loaders: thread -> (row, half); 4 A chunks + 4 B chunks ----
    const int lrow = tid >> 1, lhalf = tid & 1;
    const float* gA = A  + (size_t)(m0 + lrow) * K + lhalf * 16;
    const float* gB = Bm + (size_t)(n0 + lrow) * K + lhalf * 16;
    const uint32_t sb = smem_u32(sm);
    const uint32_t dA = sb + (uint32_t)((lhalf * 4 * 128 + lrow) * 16);
    const uint32_t dB = dA + 16384u;

#define LOADST(s, kofs) do {                                                  \
    uint32_t oa_ = dA + (uint32_t)(s) * 32768u;                               \
    uint32_t ob_ = dB + (uint32_t)(s) * 32768u;                               \
    const float* pa_ = gA + (kofs);                                           \
    const float* pb_ = gB + (kofs);                                           \
    _Pragma("unroll")                                                         \
    for (int q = 0; q < 4; q++) {                                             \
        cp16(oa_ + q * 2048u, pa_ + q * 4);                                   \
        cp16(ob_ + q * 2048u, pb_ + q * 4);                                   \
    }                                                                         \
    cp_commit();                                                              \
} while (0)

    // ---- warp/fragment indexing ----
    const int warp = tid >> 5, lane = tid & 31;
    const int wy = warp >> 2, wx = warp & 3;       // 2 x 4 warp grid
    const int m_w = wy * 64, n_w = wx * 32;
    const int r = lane >> 2, tig = lane & 3;
    const int a_base = (m_w + r) * 4 + tig;        // + mi*64, +32 for r+8, +512 for kg+1
    const int b_base = (n_w + r) * 4 + tig;        // + ni*32, +512 for kg+1

    float acc[4][4][4];
#pragma unroll
    for (int i = 0; i < 4; i++)
#pragma unroll
        for (int j = 0; j < 4; j++)
#pragma unroll
            for (int q = 0; q < 4; q++) acc[i][j][q] = 0.f;

    LOADST(0, 0);

#pragma unroll 1
    for (int it = 0; it < NCH; it++) {
        if (it + 1 < NCH) { LOADST((it + 1) & 1, (it + 1) * KC); cp_wait<1>(); }
        else              { cp_wait<0>(); }
        __syncthreads();

        const float* sA = sm + (it & 1) * 8192;
        const float* sB = sA + 4096;
#pragma unroll
        for (int kk = 0; kk < 4; kk++) {
            const int k0 = kk * 1024;              // (kk*2)*512 floats
            uint32_t bf[4][2];
#pragma unroll
            for (int ni = 0; ni < 4; ni++) {
                bf[ni][0] = __float_as_uint(sB[k0 + b_base + ni * 32]);
                bf[ni][1] = __float_as_uint(sB[k0 + 512 + b_base + ni * 32]);
            }
#pragma unroll
            for (int mi = 0; mi < 4; mi++) {
                uint32_t a0 = __float_as_uint(sA[k0 + a_base + mi * 64]);
                uint32_t a1 = __float_as_uint(sA[k0 + a_base + mi * 64 + 32]);
                uint32_t a2 = __float_as_uint(sA[k0 + 512 + a_base + mi * 64]);
                uint32_t a3 = __float_as_uint(sA[k0 + 512 + a_base + mi * 64 + 32]);
#pragma unroll
                for (int ni = 0; ni < 4; ni++)
                    mma_tf32(acc[mi][ni], a0, a1, a2, a3, bf[ni][0], bf[ni][1]);
            }
        }
        __syncthreads();
    }
#undef LOADST

    // ------------------ epilogue ------------------
    if (EPI == 0) {
#pragma unroll
        for (int ni = 0; ni < 4; ni++) {
            const int n = n0 + n_w + ni * 8 + 2 * tig;
            const float bn0 = __ldg(bias + n), bn1 = __ldg(bias + n + 1);
#pragma unroll
            for (int mi = 0; mi < 4; mi++) {
                const int m = m0 + m_w + mi * 16 + r;
                float v0 = tf32_rna(gelu_exact(acc[mi][ni][0] + bn0));
                float v1 = tf32_rna(gelu_exact(acc[mi][ni][1] + bn1));
                float v2 = tf32_rna(gelu_exact(acc[mi][ni][2] + bn0));
                float v3 = tf32_rna(gelu_exact(acc[mi][ni][3] + bn1));
                *(float2*)&C[(size_t)m * NOUT + n]       = make_float2(v0, v1);
                *(float2*)&C[(size_t)(m + 8) * NOUT + n] = make_float2(v2, v3);
            }
        }
    } else {
        // transpose via smem: tile[n_local][m_local], pitch 132
        float* tile = sm;
#pragma unroll
        for (int ni = 0; ni < 4; ni++) {
            const int n_l = n_w + ni * 8 + 2 * tig;
#pragma unroll
            for (int mi = 0; mi < 4; mi++) {
                const int m_l = m_w + mi * 16 + r;
                tile[n_l * 132 + m_l]             = acc[mi][ni][0];
                tile[(n_l + 1) * 132 + m_l]       = acc[mi][ni][1];
                tile[n_l * 132 + m_l + 8]         = acc[mi][ni][2];
                tile[(n_l + 1) * 132 + m_l + 8]   = acc[mi][ni][3];
            }
        }
        __syncthreads();
        const int bb = m0 >> 16, cc = (m0 >> 8) & 255, h0 = m0 & 255;
#pragma unroll
        for (int itr = 0; itr < 16; itr++) {
            const int nl = warp + itr * 8;
            const float bj = __ldg(bias + n0 + nl);
            size_t base = ((size_t)bb << 24) + ((size_t)(n0 + nl) << 16)
                        + ((size_t)cc << 8) + (size_t)h0 + (size_t)(lane * 4);
            float4 t  = *(float4*)&tile[nl * 132 + lane * 4];
            float4 xv = *(const float4*)&xres[base];
            *(float4*)&C[base] = make_float4(t.x + bj + xv.x, t.y + bj + xv.y,
                                             t.z + bj + xv.z, t.w + bj + xv.w);
        }
    }
}

// ---------------------------------------------------------------------------
extern "C" void kernel_launch(void* const* d_in, const int* in_sizes, int n_in,
                              void* d_out, int out_size)
{
    (void)in_sizes; (void)n_in; (void)out_size;
    const float* x   = (const float*)d_in[0];
    const float* cw  = (const float*)d_in[1];
    const float* cb  = (const float*)d_in[2];
    const float* g   = (const float*)d_in[3];
    const float* bta = (const float*)d_in[4];
    const float* w1  = (const float*)d_in[5];
    const float* b1  = (const float*)d_in[6];
    const float* w2  = (const float*)d_in[7];
    const float* b2  = (const float*)d_in[8];
    float* out = (float*)d_out;

    float *Y, *H, *W1, *W2;
    cudaGetSymbolAddress((void**)&Y,  g_Y);
    cudaGetSymbolAddress((void**)&H,  g_H);
    cudaGetSymbolAddress((void**)&W1, g_W1);
    cudaGetSymbolAddress((void**)&W2, g_W2);

    const int SMEM_BYTES = 69632;   // >= max(2*32KB pipeline, 128*132*4 tile)
    cudaFuncSetAttribute(gemm_mma<DIM, HID, 0>,
                         cudaFuncAttributeMaxDynamicSharedMemorySize, SMEM_BYTES);
    cudaFuncSetAttribute(gemm_mma<HID, DIM, 1>,
                         cudaFuncAttributeMaxDynamicSharedMemorySize, SMEM_BYTES);

    // 0) round weights to tf32 (rna) so HW truncation == RNE rounding
    round_tf32_kernel<<<(HID * DIM + 255) / 256, 256>>>(w1, W1, HID * DIM);
    round_tf32_kernel<<<(DIM * HID + 255) / 256, 256>>>(w2, W2, DIM * HID);

    // 1) depthwise conv + bias + LayerNorm(W)  (output tf32-rounded)
    conv_ln_kernel<<<dim3(DIM, DIM, BATCH), 256>>>(x, cw, cb, g, bta, Y);

    // 2) GEMM1 (K=256 -> N=1024) + bias + exact GELU   [mma.sync tf32]
    gemm_mma<DIM, HID, 0><<<dim3(HID / 128, M_ROWS / 128), 256, SMEM_BYTES>>>(
        Y, W1, b1, nullptr, H);

    // 3) GEMM2 (K=1024 -> N=256) + bias + transposed residual
    gemm_mma<HID, DIM, 1><<<dim3(DIM / 128, M_ROWS / 128), 256, SMEM_BYTES>>>(
        H, W2, b2, x, out);
}

// round 4
// speedup vs baseline: 2.7858x; 1.6452x over previous
#include <cuda_runtime.h>
#include <cstdint>

#define DIM 256
#define BATCH 2
#define M_ROWS (BATCH * DIM * DIM)   // 131072
#define HID (4 * DIM)                // 1024
#define EPS_LN 1e-5f

// Scratch (no cudaMalloc allowed). All GEMM operands stored k-permuted:
// element (row, k) lives at row*K + (k & ~7) + ((k&3)*2 + ((k>>2)&1)).
__device__ __align__(256) float g_Y[(size_t)M_ROWS * DIM];   // conv+LN out
__device__ __align__(256) float g_H[(size_t)M_ROWS * HID];   // MLP hidden
__device__ __align__(256) float g_W1[(size_t)HID * DIM];     // tf32+perm w1
__device__ __align__(256) float g_W2[(size_t)DIM * HID];     // tf32+perm w2

// ---------------------------------------------------------------------------
// helpers
// ---------------------------------------------------------------------------
__device__ __forceinline__ uint32_t smem_u32(const void* p) {
    uint32_t a;
    asm("{ .reg .u64 t; cvta.to.shared.u64 t, %1; cvt.u32.u64 %0, t; }"
        : "=r"(a) : "l"(p));
    return a;
}
__device__ __forceinline__ void cp16(uint32_t dst, const void* src) {
    asm volatile("cp.async.cg.shared.global [%0], [%1], 16;"
                 :: "r"(dst), "l"(src) : "memory");
}
__device__ __forceinline__ void cp_commit() {
    asm volatile("cp.async.commit_group;" ::: "memory");
}
template<int N> __device__ __forceinline__ void cp_wait() {
    asm volatile("cp.async.wait_group %0;" :: "n"(N) : "memory");
}
__device__ __forceinline__ float tf32_rna(float v) {
    uint32_t u;
    asm("cvt.rna.tf32.f32 %0, %1;" : "=r"(u) : "f"(v));
    return __uint_as_float(u);
}
__device__ __forceinline__ void mma_tf32(float* c, uint32_t a0, uint32_t a1,
                                         uint32_t a2, uint32_t a3,
                                         uint32_t b0, uint32_t b1) {
    asm volatile(
        "mma.sync.aligned.m16n8k8.row.col.f32.tf32.tf32.f32 "
        "{%0,%1,%2,%3}, {%4,%5,%6,%7}, {%8,%9}, {%0,%1,%2,%3};"
        : "+f"(c[0]), "+f"(c[1]), "+f"(c[2]), "+f"(c[3])
        : "r"(a0), "r"(a1), "r"(a2), "r"(a3), "r"(b0), "r"(b1));
}
__device__ __forceinline__ float gelu_exact(float v) {
    return 0.5f * v * (1.f + erff(v * 0.70710678118654752f));
}
__device__ __forceinline__ int perm8(int k) {
    return (k & ~7) | ((k & 3) * 2 + ((k >> 2) & 1));
}

// ---------------------------------------------------------------------------
// weight prep: tf32 rounding + k-permutation
// ---------------------------------------------------------------------------
__global__ void round_perm_kernel(const float* __restrict__ src,
                                  float* __restrict__ dst, int n, int K) {
    int i = blockIdx.x * blockDim.x + threadIdx.x;
    if (i < n) {
        int row = i / K, k = i - row * K;
        dst[row * K + perm8(k)] = tf32_rna(src[i]);
    }
}

// ---------------------------------------------------------------------------
// Kernel 1: depthwise 7x7 conv + bias + LayerNorm over W.
// 128 threads/block; each thread computes a 2(w) x 4(h) output patch with the
// full 7x7 weight set register-resident. Output tf32-rounded + k-permuted.
// ---------------------------------------------------------------------------
__global__ __launch_bounds__(128) void conv_ln_kernel(
    const float* __restrict__ x, const float* __restrict__ cw,
    const float* __restrict__ cb, const float* __restrict__ g,
    const float* __restrict__ bta, float* __restrict__ Y)
{
    __shared__ float s[10 * 262];
    __shared__ float swts[49];
    __shared__ float red[2][4][4];

    const int h0 = blockIdx.x * 4;
    const int c = blockIdx.y, b = blockIdx.z;
    const int tid = threadIdx.x;          // 0..127
    const int w0 = tid * 2;

    if (tid < 49) swts[tid] = cw[c * 49 + tid];

    const float* xp = x + ((size_t)(b * DIM + c)) * DIM * DIM;
    for (int i = tid; i < 10 * 262; i += 128) {
        int ro = i / 262, col = i - ro * 262;
        int hh = h0 - 3 + ro, ww = col - 3;
        float v = 0.f;
        if (hh >= 0 && hh < DIM && ww >= 0 && ww < DIM) v = xp[hh * DIM + ww];
        s[i] = v;
    }
    __syncthreads();

    float wr[49];
#pragma unroll
    for (int i = 0; i < 49; i++) wr[i] = swts[i];

    const float cbc = cb[c];
    float a0[4], a1[4];
#pragma unroll
    for (int r = 0; r < 4; r++) { a0[r] = cbc; a1[r] = cbc; }

#pragma unroll
    for (int ro = 0; ro < 10; ro++) {
        float2 p0 = *(const float2*)&s[ro * 262 + w0];
        float2 p1 = *(const float2*)&s[ro * 262 + w0 + 2];
        float2 p2 = *(const float2*)&s[ro * 262 + w0 + 4];
        float2 p3 = *(const float2*)&s[ro * 262 + w0 + 6];
        float v[8] = {p0.x, p0.y, p1.x, p1.y, p2.x, p2.y, p3.x, p3.y};
#pragma unroll
        for (int r = 0; r < 4; r++) {
            const int kh = ro - r;
            if (kh >= 0 && kh < 7) {
#pragma unroll
                for (int kw = 0; kw < 7; kw++) {
                    a0[r] += v[kw]     * wr[kh * 7 + kw];
                    a1[r] += v[kw + 1] * wr[kh * 7 + kw];
                }
            }
        }
    }

    // LayerNorm over w (256 values = 128 threads x 2)
    const int lane = tid & 31, warp = tid >> 5;
#pragma unroll
    for (int r = 0; r < 4; r++) {
        float sv = a0[r] + a1[r];
        float sq = a0[r] * a0[r] + a1[r] * a1[r];
#pragma unroll
        for (int o = 16; o; o >>= 1) {
            sv += __shfl_xor_sync(0xffffffffu, sv, o);
            sq += __shfl_xor_sync(0xffffffffu, sq, o);
        }
        if (lane == 0) { red[0][r][warp] = sv; red[1][r][warp] = sq; }
    }
    __syncthreads();

    const float gv0 = g[w0], gv1 = g[w0 + 1];
    const float bv0 = bta[w0], bv1 = bta[w0 + 1];
    const size_t rowb = ((size_t)(b * DIM + c) * DIM + h0) * DIM;
    const int pw0 = perm8(w0), pw1 = perm8(w0 + 1);
#pragma unroll
    for (int r = 0; r < 4; r++) {
        float S  = red[0][r][0] + red[0][r][1] + red[0][r][2] + red[0][r][3];
        float S2 = red[1][r][0] + red[1][r][1] + red[1][r][2] + red[1][r][3];
        float mu  = S * (1.f / 256.f);
        float var = S2 * (1.f / 256.f) - mu * mu;
        float inv = rsqrtf(var + EPS_LN);
        Y[rowb + (size_t)r * DIM + pw0] = tf32_rna((a0[r] - mu) * inv * gv0 + bv0);
        Y[rowb + (size_t)r * DIM + pw1] = tf32_rna((a1[r] - mu) * inv * gv1 + bv1);
    }
}

// ---------------------------------------------------------------------------
// mma.sync tf32 GEMM on k-permuted operands.
// 128x128 CTA tile, BK=32, 3-stage cp.async pipeline, 8 warps (2m x 4n),
// warp tile 64x32. SMEM per stage: A [4 kg][128 row][8 perm-k] + B same.
// All fragment loads are conflict-free LDS.64.
// EPI==0: gelu(acc + bias[n]) tf32-rounded -> C row-major [M,NOUT], n-permuted
// EPI==1: acc + bias[n] + x -> transposed residual store out[b,n,c,h]
// ---------------------------------------------------------------------------
template<int K, int NOUT, int EPI>
__global__ void __launch_bounds__(256, 2) gemm_mma(
    const float* __restrict__ A, const float* __restrict__ Bm,
    const float* __restrict__ bias, const float* __restrict__ xres,
    float* __restrict__ C)
{
    constexpr int KC = 32, NCH = K / KC;
    extern __shared__ float sm[];   // stage s at s*8192 floats (A 4096, B 4096)

    const int tid = threadIdx.x;
    const int m0 = blockIdx.y * 128, n0 = blockIdx.x * 128;

    // loaders: row = tid>>1 (0..127), half = tid&1 -> 16B of each kg
    const int lrow = tid >> 1, lhalf = tid & 1;
    const float* gA = A  + (size_t)(m0 + lrow) * K + lhalf * 4;
    const float* gB = Bm + (size_t)(n0 + lrow) * K + lhalf * 4;
    const uint32_t sb = smem_u32(sm);
    const uint32_t dA = sb + (uint32_t)(lrow * 32 + lhalf * 16);
    const uint32_t dB = dA + 16384u;

#define LOADST(s, kofs) do {                                                  \
    uint32_t oa_ = dA + (uint32_t)(s) * 32768u;                               \
    uint32_t ob_ = dB + (uint32_t)(s) * 32768u;                               \
    const float* pa_ = gA + (kofs);                                           \
    const float* pb_ = gB + (kofs);                                           \
    _Pragma("unroll")                                                         \
    for (int q = 0; q < 4; q++) {                                             \
        cp16(oa_ + q * 4096u, pa_ + q * 8);                                   \
        cp16(ob_ + q * 4096u, pb_ + q * 8);                                   \
    }                                                                         \
    cp_commit();                                                              \
} while (0)

    const int warp = tid >> 5, lane = tid & 31;
    const int wy = warp >> 2, wx = warp & 3;       // 2 x 4 warp grid
    const int m_w = wy * 64, n_w = wx * 32;
    const int r = lane >> 2, tig = lane & 3;
    const int ao = (m_w + r) * 8 + tig * 2;                // A float2 base
    const int bo = 4096 + (n_w + r) * 8 + tig * 2;         // B float2 base

    float acc[4][4][4] = {};

    LOADST(0, 0);
    LOADST(1, KC);

#pragma unroll 1
    for (int it = 0; it < NCH; it++) {
        if (it < NCH - 1) cp_wait<1>(); else cp_wait<0>();
        __syncthreads();
        if (it + 2 < NCH) LOADST((it + 2) % 3, (it + 2) * KC);

        const float* st = sm + (it % 3) * 8192;
#pragma unroll
        for (int kk = 0; kk < 4; kk++) {
            const float* sk = st + kk * 1024;
            float2 bf[4];
#pragma unroll
            for (int ni = 0; ni < 4; ni++)
                bf[ni] = *(const float2*)&sk[bo + ni * 64];
#pragma unroll
            for (int mi = 0; mi < 4; mi++) {
                float2 lo = *(const float2*)&sk[ao + mi * 128];
                float2 hi = *(const float2*)&sk[ao + mi * 128 + 64];
#pragma unroll
                for (int ni = 0; ni < 4; ni++)
                    mma_tf32(acc[mi][ni],
                             __float_as_uint(lo.x), __float_as_uint(hi.x),
                             __float_as_uint(lo.y), __float_as_uint(hi.y),
                             __float_as_uint(bf[ni].x), __float_as_uint(bf[ni].y));
            }
        }
    }
#undef LOADST

    // ------------------ epilogue ------------------
    if (EPI == 0) {
#pragma unroll
        for (int ni = 0; ni < 4; ni++) {
            const int n = n0 + n_w + ni * 8 + 2 * tig;
            const float bn0 = __ldg(bias + n), bn1 = __ldg(bias + n + 1);
            const int np0 = perm8(n) - n0, np1 = perm8(n + 1) - n0;
#pragma unroll
            for (int mi = 0; mi < 4; mi++) {
                const size_t m = (size_t)(m0 + m_w + mi * 16 + r);
                float* C0 = C + m * NOUT + n0;
                float* C8 = C0 + (size_t)8 * NOUT;
                C0[np0] = tf32_rna(gelu_exact(acc[mi][ni][0] + bn0));
                C0[np1] = tf32_rna(gelu_exact(acc[mi][ni][1] + bn1));
                C8[np0] = tf32_rna(gelu_exact(acc[mi][ni][2] + bn0));
                C8[np1] = tf32_rna(gelu_exact(acc[mi][ni][3] + bn1));
            }
        }
    } else {
        __syncthreads();   // pipeline smem reused as transpose tile
        float* tile = sm;
#pragma unroll
        for (int ni = 0; ni < 4; ni++) {
            const int n_l = n_w + ni * 8 + 2 * tig;
#pragma unroll
            for (int mi = 0; mi < 4; mi++) {
                const int m_l = m_w + mi * 16 + r;
                tile[n_l * 132 + m_l]           = acc[mi][ni][0];
                tile[(n_l + 1) * 132 + m_l]     = acc[mi][ni][1];
                tile[n_l * 132 + m_l + 8]       = acc[mi][ni][2];
                tile[(n_l + 1) * 132 + m_l + 8] = acc[mi][ni][3];
            }
        }
        __syncthreads();
        const int bb = m0 >> 16, cc = (m0 >> 8) & 255, h0 = m0 & 255;
#pragma unroll
        for (int itr = 0; itr < 16; itr++) {
            const int nl = warp + itr * 8;
            const float bj = __ldg(bias + n0 + nl);
            size_t base = ((size_t)bb << 24) + ((size_t)(n0 + nl) << 16)
                        + ((size_t)cc << 8) + (size_t)h0 + (size_t)(lane * 4);
            float4 t  = *(float4*)&tile[nl * 132 + lane * 4];
            float4 xv = *(const float4*)&xres[base];
            *(float4*)&C[base] = make_float4(t.x + bj + xv.x, t.y + bj + xv.y,
                                             t.z + bj + xv.z, t.w + bj + xv.w);
        }
    }
}

// ---------------------------------------------------------------------------
extern "C" void kernel_launch(void* const* d_in, const int* in_sizes, int n_in,
                              void* d_out, int out_size)
{
    (void)in_sizes; (void)n_in; (void)out_size;
    const float* x   = (const float*)d_in[0];
    const float* cw  = (const float*)d_in[1];
    const float* cb  = (const float*)d_in[2];
    const float* g   = (const float*)d_in[3];
    const float* bta = (const float*)d_in[4];
    const float* w1  = (const float*)d_in[5];
    const float* b1  = (const float*)d_in[6];
    const float* w2  = (const float*)d_in[7];
    const float* b2  = (const float*)d_in[8];
    float* out = (float*)d_out;

    float *Y, *H, *W1, *W2;
    cudaGetSymbolAddress((void**)&Y,  g_Y);
    cudaGetSymbolAddress((void**)&H,  g_H);
    cudaGetSymbolAddress((void**)&W1, g_W1);
    cudaGetSymbolAddress((void**)&W2, g_W2);

    const int SMEM_BYTES = 98304;   // 3 stages x 32KB
    cudaFuncSetAttribute(gemm_mma<DIM, HID, 0>,
                         cudaFuncAttributeMaxDynamicSharedMemorySize, SMEM_BYTES);
    cudaFuncSetAttribute(gemm_mma<HID, DIM, 1>,
                         cudaFuncAttributeMaxDynamicSharedMemorySize, SMEM_BYTES);

    // 0) weights -> tf32-rounded + k-permuted scratch
    round_perm_kernel<<<(HID * DIM + 255) / 256, 256>>>(w1, W1, HID * DIM, DIM);
    round_perm_kernel<<<(DIM * HID + 255) / 256, 256>>>(w2, W2, DIM * HID, HID);

    // 1) depthwise conv + bias + LayerNorm(W) -> Y (tf32, k-permuted)
    conv_ln_kernel<<<dim3(DIM / 4, DIM, BATCH), 128>>>(x, cw, cb, g, bta, Y);

    // 2) GEMM1 (K=256 -> N=1024) + bias + exact GELU -> H (tf32, n-permuted)
    gemm_mma<DIM, HID, 0><<<dim3(HID / 128, M_ROWS / 128), 256, SMEM_BYTES>>>(
        Y, W1, b1, nullptr, H);

    // 3) GEMM2 (K=1024 -> N=256) + bias + transposed residual -> out
    gemm_mma<HID, DIM, 1><<<dim3(DIM / 128, M_ROWS / 128), 256, SMEM_BYTES>>>(
        H, W2, b2, x, out);
}

// round 5
// speedup vs baseline: 3.6024x; 1.2931x over previous
#include <cuda_runtime.h>
#include <cuda_bf16.h>
#include <cstdint>

#define DIM 256
#define BATCH 2
#define M_ROWS (BATCH * DIM * DIM)   // 131072
#define HID (4 * DIM)                // 1024
#define EPS_LN 1e-5f

// Scratch (no cudaMalloc). bf16 GEMM operands, pair-permuted k layout:
// element (row,k) at row*K + (k&~15) + pos*2 + (k&1), p=(k>>1)&7,
// pos = (p&3)*2 + (p>>2). Fragments then load as single LDS.64.
__device__ __align__(256) __nv_bfloat16 g_Y[(size_t)M_ROWS * DIM];
__device__ __align__(256) __nv_bfloat16 g_H[(size_t)M_ROWS * HID];
__device__ __align__(256) __nv_bfloat16 g_W1[(size_t)HID * DIM];
__device__ __align__(256) __nv_bfloat16 g_W2[(size_t)DIM * HID];

// ---------------------------------------------------------------------------
// helpers
// ---------------------------------------------------------------------------
__device__ __forceinline__ uint32_t smem_u32(const void* p) {
    uint32_t a;
    asm("{ .reg .u64 t; cvta.to.shared.u64 t, %1; cvt.u32.u64 %0, t; }"
        : "=r"(a) : "l"(p));
    return a;
}
__device__ __forceinline__ void cp16(uint32_t dst, const void* src) {
    asm volatile("cp.async.cg.shared.global [%0], [%1], 16;"
                 :: "r"(dst), "l"(src) : "memory");
}
__device__ __forceinline__ void cp_commit() {
    asm volatile("cp.async.commit_group;" ::: "memory");
}
template<int N> __device__ __forceinline__ void cp_wait() {
    asm volatile("cp.async.wait_group %0;" :: "n"(N) : "memory");
}
__device__ __forceinline__ void mma_bf16(float* c, uint32_t a0, uint32_t a1,
                                         uint32_t a2, uint32_t a3,
                                         uint32_t b0, uint32_t b1) {
    asm volatile(
        "mma.sync.aligned.m16n8k16.row.col.f32.bf16.bf16.f32 "
        "{%0,%1,%2,%3}, {%4,%5,%6,%7}, {%8,%9}, {%0,%1,%2,%3};"
        : "+f"(c[0]), "+f"(c[1]), "+f"(c[2]), "+f"(c[3])
        : "r"(a0), "r"(a1), "r"(a2), "r"(a3), "r"(b0), "r"(b1));
}
__device__ __forceinline__ float gelu_exact(float v) {
    return 0.5f * v * (1.f + erff(v * 0.70710678118654752f));
}
__device__ __forceinline__ int permpair(int k) {
    int p = (k >> 1) & 7;
    return (k & ~15) | (((((p & 3) << 1) | (p >> 2)) << 1) | (k & 1));
}

// ---------------------------------------------------------------------------
// weight prep: bf16 conversion + pair-permutation
// ---------------------------------------------------------------------------
__global__ void round_perm_bf16(const float* __restrict__ src,
                                __nv_bfloat16* __restrict__ dst, int n, int K) {
    int i = blockIdx.x * blockDim.x + threadIdx.x;
    if (i < n) {
        int row = i / K, k = i - row * K;
        dst[row * K + permpair(k)] = __float2bfloat16(src[i]);
    }
}

// ---------------------------------------------------------------------------
// Kernel 1: depthwise 7x7 conv + bias + LayerNorm over W.
// 128 threads/block, 2(w) x 4(h) patch per thread, weights in registers.
// Output: bf16, pair-permuted along w (= GEMM1's k).
// ---------------------------------------------------------------------------
__global__ __launch_bounds__(128) void conv_ln_kernel(
    const float* __restrict__ x, const float* __restrict__ cw,
    const float* __restrict__ cb, const float* __restrict__ g,
    const float* __restrict__ bta, __nv_bfloat16* __restrict__ Y)
{
    __shared__ float s[10 * 262];
    __shared__ float swts[49];
    __shared__ float red[2][4][4];

    const int h0 = blockIdx.x * 4;
    const int c = blockIdx.y, b = blockIdx.z;
    const int tid = threadIdx.x;
    const int w0 = tid * 2;

    if (tid < 49) swts[tid] = cw[c * 49 + tid];

    const float* xp = x + ((size_t)(b * DIM + c)) * DIM * DIM;
    for (int i = tid; i < 10 * 262; i += 128) {
        int ro = i / 262, col = i - ro * 262;
        int hh = h0 - 3 + ro, ww = col - 3;
        float v = 0.f;
        if (hh >= 0 && hh < DIM && ww >= 0 && ww < DIM) v = xp[hh * DIM + ww];
        s[i] = v;
    }
    __syncthreads();

    float wr[49];
#pragma unroll
    for (int i = 0; i < 49; i++) wr[i] = swts[i];

    const float cbc = cb[c];
    float a0[4], a1[4];
#pragma unroll
    for (int r = 0; r < 4; r++) { a0[r] = cbc; a1[r] = cbc; }

#pragma unroll
    for (int ro = 0; ro < 10; ro++) {
        float2 p0 = *(const float2*)&s[ro * 262 + w0];
        float2 p1 = *(const float2*)&s[ro * 262 + w0 + 2];
        float2 p2 = *(const float2*)&s[ro * 262 + w0 + 4];
        float2 p3 = *(const float2*)&s[ro * 262 + w0 + 6];
        float v[8] = {p0.x, p0.y, p1.x, p1.y, p2.x, p2.y, p3.x, p3.y};
#pragma unroll
        for (int r = 0; r < 4; r++) {
            const int kh = ro - r;
            if (kh >= 0 && kh < 7) {
#pragma unroll
                for (int kw = 0; kw < 7; kw++) {
                    a0[r] += v[kw]     * wr[kh * 7 + kw];
                    a1[r] += v[kw + 1] * wr[kh * 7 + kw];
                }
            }
        }
    }

    const int lane = tid & 31, warp = tid >> 5;
#pragma unroll
    for (int r = 0; r < 4; r++) {
        float sv = a0[r] + a1[r];
        float sq = a0[r] * a0[r] + a1[r] * a1[r];
#pragma unroll
        for (int o = 16; o; o >>= 1) {
            sv += __shfl_xor_sync(0xffffffffu, sv, o);
            sq += __shfl_xor_sync(0xffffffffu, sq, o);
        }
        if (lane == 0) { red[0][r][warp] = sv; red[1][r][warp] = sq; }
    }
    __syncthreads();

    const float gv0 = g[w0], gv1 = g[w0 + 1];
    const float bv0 = bta[w0], bv1 = bta[w0 + 1];
    const size_t rowb = ((size_t)(b * DIM + c) * DIM + h0) * DIM;
    const int p = tid & 7, pos = ((p & 3) << 1) | (p >> 2);
    const int pw = (w0 & ~15) + pos * 2;
#pragma unroll
    for (int r = 0; r < 4; r++) {
        float S  = red[0][r][0] + red[0][r][1] + red[0][r][2] + red[0][r][3];
        float S2 = red[1][r][0] + red[1][r][1] + red[1][r][2] + red[1][r][3];
        float mu  = S * (1.f / 256.f);
        float var = S2 * (1.f / 256.f) - mu * mu;
        float inv = rsqrtf(var + EPS_LN);
        __nv_bfloat162 o;
        o.x = __float2bfloat16((a0[r] - mu) * inv * gv0 + bv0);
        o.y = __float2bfloat16((a1[r] - mu) * inv * gv1 + bv1);
        *(__nv_bfloat162*)&Y[rowb + (size_t)r * DIM + pw] = o;
    }
}

// ---------------------------------------------------------------------------
// bf16 m16n8k16 GEMM on pair-permuted operands.
// 128x128 CTA tile, KC=32, 4-stage cp.async pipeline, 8 warps (2m x 4n),
// warp tile 64x32. Stage: [A kg0|A kg1|B kg0|B kg1] x 4096B, rows of 32B.
// EPI==0: gelu(acc+bias) -> bf16 C [M,NOUT], pair-permuted n (= GEMM2 k)
// EPI==1: acc + bias + x -> fp32 transposed residual store out[b,n,c,h]
// ---------------------------------------------------------------------------
template<int K, int NOUT, int EPI>
__global__ void __launch_bounds__(256, 2) gemm_bf16(
    const __nv_bfloat16* __restrict__ A, const __nv_bfloat16* __restrict__ Bm,
    const float* __restrict__ bias, const float* __restrict__ xres, void* Cv)
{
    constexpr int KC = 32, NCH = K / KC;
    extern __shared__ char smem[];

    const int tid = threadIdx.x;
    const int m0 = blockIdx.y * 128, n0 = blockIdx.x * 128;

    const int lrow = tid >> 1, lhalf = tid & 1;
    const char* gA = (const char*)(A  + (size_t)(m0 + lrow) * K) + lhalf * 32;
    const char* gB = (const char*)(Bm + (size_t)(n0 + lrow) * K) + lhalf * 32;
    const uint32_t sb = smem_u32(smem);
    const uint32_t dA = sb + (uint32_t)lhalf * 4096u + (uint32_t)lrow * 32u;
    const uint32_t dB = dA + 8192u;

#define LOADST(s, kofs) do {                                                  \
    uint32_t oa_ = dA + (uint32_t)(s) * 16384u;                               \
    uint32_t ob_ = dB + (uint32_t)(s) * 16384u;                               \
    const char* pa_ = gA + (size_t)(kofs) * 2;                                \
    const char* pb_ = gB + (size_t)(kofs) * 2;                                \
    cp16(oa_, pa_); cp16(oa_ + 16u, pa_ + 16);                                \
    cp16(ob_, pb_); cp16(ob_ + 16u, pb_ + 16);                                \
    cp_commit();                                                              \
} while (0)

    const int warp = tid >> 5, lane = tid & 31;
    const int wy = warp >> 2, wx = warp & 3;
    const int m_w = wy * 64, n_w = wx * 32;
    const int r = lane >> 2, tig = lane & 3;
    const uint32_t aoff = (uint32_t)((m_w + r) * 32 + tig * 8);
    const uint32_t boff = 8192u + (uint32_t)((n_w + r) * 32 + tig * 8);

    float acc[4][4][4] = {};

    LOADST(0, 0); LOADST(1, KC); LOADST(2, 2 * KC);

#pragma unroll 1
    for (int it = 0; it < NCH; it++) {
        cp_wait<2>();
        __syncthreads();
        if (it + 3 < NCH) LOADST((it + 3) & 3, (it + 3) * KC);
        else cp_commit();   // keep group count exact for wait<2>

        const char* st = smem + (size_t)(it & 3) * 16384;
#pragma unroll
        for (int kg = 0; kg < 2; kg++) {
            const char* sk = st + kg * 4096;
            uint2 bf[4];
#pragma unroll
            for (int ni = 0; ni < 4; ni++)
                bf[ni] = *(const uint2*)(sk + boff + ni * 256);
#pragma unroll
            for (int mi = 0; mi < 4; mi++) {
                uint2 alo = *(const uint2*)(sk + aoff + mi * 512);
                uint2 ahi = *(const uint2*)(sk + aoff + mi * 512 + 256);
#pragma unroll
                for (int ni = 0; ni < 4; ni++)
                    mma_bf16(acc[mi][ni], alo.x, ahi.x, alo.y, ahi.y,
                             bf[ni].x, bf[ni].y);
            }
        }
    }
#undef LOADST

    // ------------------ epilogue ------------------
    if (EPI == 0) {
        __nv_bfloat16* C = (__nv_bfloat16*)Cv;
#pragma unroll
        for (int ni = 0; ni < 4; ni++) {
            const int n = n0 + n_w + ni * 8 + 2 * tig;
            const float bn0 = __ldg(bias + n), bn1 = __ldg(bias + n + 1);
            const int pp = (n >> 1) & 7;
            const int pw = (n & ~15) + ((((pp & 3) << 1) | (pp >> 2)) << 1);
#pragma unroll
            for (int mi = 0; mi < 4; mi++) {
                const size_t m = (size_t)(m0 + m_w + mi * 16 + r);
                __nv_bfloat162 v01, v23;
                v01.x = __float2bfloat16(gelu_exact(acc[mi][ni][0] + bn0));
                v01.y = __float2bfloat16(gelu_exact(acc[mi][ni][1] + bn1));
                v23.x = __float2bfloat16(gelu_exact(acc[mi][ni][2] + bn0));
                v23.y = __float2bfloat16(gelu_exact(acc[mi][ni][3] + bn1));
                *(__nv_bfloat162*)&C[m * NOUT + pw]              = v01;
                *(__nv_bfloat162*)&C[(m + 8) * NOUT + pw]        = v23;
            }
        }
    } else {
        float* C = (float*)Cv;
        __syncthreads();
        float* tile = (float*)smem;
#pragma unroll
        for (int ni = 0; ni < 4; ni++) {
            const int n_l = n_w + ni * 8 + 2 * tig;
#pragma unroll
            for (int mi = 0; mi < 4; mi++) {
                const int m_l = m_w + mi * 16 + r;
                tile[n_l * 132 + m_l]           = acc[mi][ni][0];
                tile[(n_l + 1) * 132 + m_l]     = acc[mi][ni][1];
                tile[n_l * 132 + m_l + 8]       = acc[mi][ni][2];
                tile[(n_l + 1) * 132 + m_l + 8] = acc[mi][ni][3];
            }
        }
        __syncthreads();
        const int bb = m0 >> 16, cc = (m0 >> 8) & 255, h0 = m0 & 255;
#pragma unroll
        for (int itr = 0; itr < 16; itr++) {
            const int nl = warp + itr * 8;
            const float bj = __ldg(bias + n0 + nl);
            size_t base = ((size_t)bb << 24) + ((size_t)(n0 + nl) << 16)
                        + ((size_t)cc << 8) + (size_t)h0 + (size_t)(lane * 4);
            float4 t  = *(float4*)&tile[nl * 132 + lane * 4];
            float4 xv = *(const float4*)&xres[base];
            *(float4*)&C[base] = make_float4(t.x + bj + xv.x, t.y + bj + xv.y,
                                             t.z + bj + xv.z, t.w + bj + xv.w);
        }
    }
}

// ---------------------------------------------------------------------------
extern "C" void kernel_launch(void* const* d_in, const int* in_sizes, int n_in,
                              void* d_out, int out_size)
{
    (void)in_sizes; (void)n_in; (void)out_size;
    const float* x   = (const float*)d_in[0];
    const float* cw  = (const float*)d_in[1];
    const float* cb  = (const float*)d_in[2];
    const float* g   = (const float*)d_in[3];
    const float* bta = (const float*)d_in[4];
    const float* w1  = (const float*)d_in[5];
    const float* b1  = (const float*)d_in[6];
    const float* w2  = (const float*)d_in[7];
    const float* b2  = (const float*)d_in[8];
    float* out = (float*)d_out;

    __nv_bfloat16 *Y, *H, *W1, *W2;
    cudaGetSymbolAddress((void**)&Y,  g_Y);
    cudaGetSymbolAddress((void**)&H,  g_H);
    cudaGetSymbolAddress((void**)&W1, g_W1);
    cudaGetSymbolAddress((void**)&W2, g_W2);

    const int SMEM_BYTES = 69632;   // 4 stages x 16KB pipeline; 67.6KB EPI1 tile
    cudaFuncSetAttribute(gemm_bf16<DIM, HID, 0>,
                         cudaFuncAttributeMaxDynamicSharedMemorySize, SMEM_BYTES);
    cudaFuncSetAttribute(gemm_bf16<HID, DIM, 1>,
                         cudaFuncAttributeMaxDynamicSharedMemorySize, SMEM_BYTES);

    // 0) weights -> bf16 + pair-permuted scratch
    round_perm_bf16<<<(HID * DIM + 255) / 256, 256>>>(w1, W1, HID * DIM, DIM);
    round_perm_bf16<<<(DIM * HID + 255) / 256, 256>>>(w2, W2, DIM * HID, HID);

    // 1) depthwise conv + bias + LayerNorm(W) -> Y (bf16, permuted)
    conv_ln_kernel<<<dim3(DIM / 4, DIM, BATCH), 128>>>(x, cw, cb, g, bta, Y);

    // 2) GEMM1 (K=256 -> N=1024) + bias + exact GELU -> H (bf16, permuted)
    gemm_bf16<DIM, HID, 0><<<dim3(HID / 128, M_ROWS / 128), 256, SMEM_BYTES>>>(
        Y, W1, b1, nullptr, H);

    // 3) GEMM2 (K=1024 -> N=256) + bias + transposed residual -> out (fp32)
    gemm_bf16<HID, DIM, 1><<<dim3(DIM / 128, M_ROWS / 128), 256, SMEM_BYTES>>>(
        H, W2, b2, x, out);
}